// round 16
// baseline (speedup 1.0000x reference)
#include <cuda_runtime.h>
#include <cstdint>

#define NN 3072
#define HH 64
#define VV 4
#define SPLITS 4
#define JSPLIT 4
#define JLOC (NN / JSPLIT)
#define FULLMASK 0xFFFFFFFFu
#define NEGBIG (-1e30f)

// ------------------- scratch (device globals; no allocations) -------------------
__device__ float g_Wh[NN * HH];       // [tile][h=64][perm(j)=64], tf32-rounded
__device__ float g_el[NN];
__device__ float g_er[NN];
__device__ float g_hgat[VV * NN * HH];
__device__ float g_q[VV * NN * HH];   // tf32-rounded, cols pair-permuted
__device__ float g_k[VV * NN * HH];   // tf32-rounded, cols pair-permuted
__device__ float g_v[VV * NN * HH];   // [tile][d=64][perm(seq)=64], tf32-rounded
__device__ float g_vals[VV * NN * HH];
__device__ float g_po[8 * VV * NN * HH];
__device__ float g_pm[8 * VV * NN];
__device__ float g_pl[8 * VV * NN];

__device__ __forceinline__ uint32_t f2tf(float f) {
    uint32_t u;
    asm("cvt.rna.tf32.f32 %0, %1;" : "=r"(u) : "f"(f));
    return u;
}
__device__ __forceinline__ float tfround(float f) { return __uint_as_float(f2tf(f)); }

__device__ __forceinline__ int permcol(int c) {
    return (c & ~7) | (((c & 3) << 1) | ((c >> 2) & 1));
}

__device__ __forceinline__ void mma_tf32(float* d, const uint32_t* a, uint32_t b0, uint32_t b1) {
    asm volatile(
        "mma.sync.aligned.m16n8k8.row.col.f32.tf32.tf32.f32 "
        "{%0,%1,%2,%3}, {%4,%5,%6,%7}, {%8,%9}, {%0,%1,%2,%3};"
        : "+f"(d[0]), "+f"(d[1]), "+f"(d[2]), "+f"(d[3])
        : "r"(a[0]), "r"(a[1]), "r"(a[2]), "r"(a[3]), "r"(b0), "r"(b1));
}

__device__ __forceinline__ void cp16(float* dst, const float* src) {
    uint32_t d = (uint32_t)__cvta_generic_to_shared(dst);
    asm volatile("cp.async.ca.shared.global [%0], [%1], 16;\n" :: "r"(d), "l"(src));
}
__device__ __forceinline__ void cp16cg(float* dst, const float* src) {
    uint32_t d = (uint32_t)__cvta_generic_to_shared(dst);
    asm volatile("cp.async.cg.shared.global [%0], [%1], 16;\n" :: "r"(d), "l"(src));
}

// ------------------- K1: Wh = X @ W ; el ; er. g_Wh stored [tile][h][perm(j)] -------------------
__global__ void k1_wh(const float* __restrict__ x, const float* __restrict__ W,
                      const float* __restrict__ a) {
    __shared__ float Wsm[64 * 64];
    __shared__ float a_sm[128];
    int tid = threadIdx.x;
    for (int i = tid; i < 64 * 64; i += 256) Wsm[i] = W[i];
    if (tid < 128) a_sm[tid] = a[tid];
    __syncthreads();
    int warp = tid >> 5, lane = tid & 31;
    int row = blockIdx.x * 8 + warp;
    const float* xr = x + row * 64;
    float x0 = xr[lane], x1 = xr[lane + 32];
    float wh0 = 0.f, wh1 = 0.f;
#pragma unroll
    for (int k = 0; k < 64; k++) {
        float xk = __shfl_sync(FULLMASK, (k < 32) ? x0 : x1, k & 31);
        wh0 += xk * Wsm[k * 64 + lane];
        wh1 += xk * Wsm[k * 64 + lane + 32];
    }
    size_t tb = (size_t)(row >> 6) * 4096;
    int pj = permcol(row & 63);
    g_Wh[tb + (size_t)lane * 64 + pj]        = tfround(wh0);
    g_Wh[tb + (size_t)(lane + 32) * 64 + pj] = tfround(wh1);
    float pl = wh0 * a_sm[lane] + wh1 * a_sm[lane + 32];
    float pr = wh0 * a_sm[64 + lane] + wh1 * a_sm[96 + lane];
#pragma unroll
    for (int o = 16; o; o >>= 1) {
        pl += __shfl_xor_sync(FULLMASK, pl, o);
        pr += __shfl_xor_sync(FULLMASK, pr, o);
    }
    if (lane == 0) { g_el[row] = pl; g_er[row] = pr; }
}

// ------------------- K2: tensor-core GAT, cp.async-staged, float2 B-frags -------------------
#define WHPAD 72
#define ADJPAD 132
#define K2_SMEM ((2 * 64 * WHPAD + 2 * 64 * ADJPAD + JLOC) * 4)

__global__ void __launch_bounds__(256) k2_gat(const float* __restrict__ adj) {
    extern __shared__ float sm2[];
    float* whs0  = sm2;                          // [2 tile][64 h][WHPAD] (perm j cols)
    float* adjs0 = sm2 + 2 * 64 * WHPAD;         // [2 buf][64 row][ADJPAD]
    float* ers   = adjs0 + 2 * 64 * ADJPAD;      // [JLOC]
    __shared__ float wred[8];
    int tid = threadIdx.x, warp = tid >> 5, lane = tid & 31;
    int g = lane >> 2, t = lane & 3;
    int grp = warp >> 2, rw = warp & 3;
    int v = blockIdx.y, row0 = blockIdx.x * 64, sp = blockIdx.z;
    const int JT_PER = NN / 128 / JSPLIT;   // 6
    int jt0 = sp * JT_PER;

    {
        const float* Asrc = adj + ((size_t)v * NN + row0) * NN + (size_t)jt0 * 128;
        for (int i = tid; i < 2048; i += 256) {
            int r = i >> 5, c4 = i & 31;
            cp16cg(&adjs0[r * ADJPAD + c4 * 4], Asrc + (size_t)r * NN + c4 * 4);
        }
        asm volatile("cp.async.commit_group;\n");
    }

    float mx = NEGBIG;
    for (int i = tid; i < NN; i += 256) mx = fmaxf(mx, __ldg(&g_er[i]));
#pragma unroll
    for (int o = 16; o; o >>= 1) mx = fmaxf(mx, __shfl_xor_sync(FULLMASK, mx, o));
    if (lane == 0) wred[warp] = mx;
    __syncthreads();
    float ermax = wred[0];
#pragma unroll
    for (int i = 1; i < 8; i++) ermax = fmaxf(ermax, wred[i]);

    for (int i = tid; i < JLOC; i += 256) ers[i] = __ldg(&g_er[sp * JLOC + i]);

    int r0 = row0 + rw * 16 + g;
    float el0 = __ldg(&g_el[r0]), el1 = __ldg(&g_el[r0 + 8]);
    float m0 = el0 + ermax; m0 = (m0 > 0.f) ? m0 : 0.2f * m0;
    float m1 = el1 + ermax; m1 = (m1 > 0.f) ? m1 : 0.2f * m1;

    float o_[8][4];
#pragma unroll
    for (int db = 0; db < 8; db++) { o_[db][0] = o_[db][1] = o_[db][2] = o_[db][3] = 0.f; }
    float z0 = 0.f, z1 = 0.f;
    int lr0 = rw * 16 + g, lr1 = lr0 + 8;

    for (int jj = 0; jj < JT_PER; jj++) {
        int jt2 = jt0 + jj;
        __syncthreads();
        const float* Wsrc = g_Wh + (size_t)jt2 * 2 * 4096;
        for (int i = tid; i < 2048; i += 256) {
            int b = i >> 10, ii = i & 1023;
            int h = ii >> 4, c4 = ii & 15;
            cp16(&whs0[b * 64 * WHPAD + h * WHPAD + c4 * 4], Wsrc + b * 4096 + h * 64 + c4 * 4);
        }
        asm volatile("cp.async.commit_group;\n");
        if (jj + 1 < JT_PER) {
            const float* Asrc = adj + ((size_t)v * NN + row0) * NN + (size_t)(jt2 + 1) * 128;
            float* ad = adjs0 + ((jj + 1) & 1) * 64 * ADJPAD;
            for (int i = tid; i < 2048; i += 256) {
                int r = i >> 5, c4 = i & 31;
                cp16cg(&ad[r * ADJPAD + c4 * 4], Asrc + (size_t)r * NN + c4 * 4);
            }
            asm volatile("cp.async.commit_group;\n");
            asm volatile("cp.async.wait_group 1;\n");
        } else {
            asm volatile("cp.async.wait_group 0;\n");
        }
        __syncthreads();
        const float* wh = whs0 + grp * 64 * WHPAD;
        const float* ad = adjs0 + (jj & 1) * 64 * ADJPAD;
        int lj0 = jj * 128 + grp * 64;
        int ljc0 = grp * 64;
#pragma unroll
        for (int kc = 0; kc < 8; kc++) {
            int ljc = ljc0 + kc * 8;
            float a00 = ad[lr0 * ADJPAD + ljc + t];
            float a10 = ad[lr1 * ADJPAD + ljc + t];
            float a01 = ad[lr0 * ADJPAD + ljc + t + 4];
            float a11 = ad[lr1 * ADJPAD + ljc + t + 4];
            int lj = lj0 + kc * 8;
            float erA = ers[lj + t], erB = ers[lj + t + 4];
            float eA0 = el0 + erA; eA0 = (eA0 > 0.f) ? eA0 : 0.2f * eA0;
            float eA1 = el1 + erA; eA1 = (eA1 > 0.f) ? eA1 : 0.2f * eA1;
            float eB0 = el0 + erB; eB0 = (eB0 > 0.f) ? eB0 : 0.2f * eB0;
            float eB1 = el1 + erB; eB1 = (eB1 > 0.f) ? eB1 : 0.2f * eB1;
            float p00 = (a00 > 0.f) ? tfround(__expf(eA0 - m0)) : 0.f;
            float p10 = (a10 > 0.f) ? tfround(__expf(eA1 - m1)) : 0.f;
            float p01 = (a01 > 0.f) ? tfround(__expf(eB0 - m0)) : 0.f;
            float p11 = (a11 > 0.f) ? tfround(__expf(eB1 - m1)) : 0.f;
            z0 += p00 + p01;
            z1 += p10 + p11;
            uint32_t af[4] = {__float_as_uint(p00), __float_as_uint(p10),
                              __float_as_uint(p01), __float_as_uint(p11)};
#pragma unroll
            for (int db = 0; db < 8; db++) {
                float2 kv = *(const float2*)&wh[(db * 8 + g) * WHPAD + kc * 8 + 2 * t];
                mma_tf32(o_[db], af, __float_as_uint(kv.x), __float_as_uint(kv.y));
            }
        }
    }
    __syncthreads();
    float* scr = whs0;
    if (grp == 1) {
        float* p = scr + (rw * 32 + lane) * 34;
#pragma unroll
        for (int db = 0; db < 8; db++) {
            p[db * 4] = o_[db][0]; p[db * 4 + 1] = o_[db][1];
            p[db * 4 + 2] = o_[db][2]; p[db * 4 + 3] = o_[db][3];
        }
        p[32] = z0; p[33] = z1;
    }
    __syncthreads();
    if (grp == 0) {
        const float* p = scr + (rw * 32 + lane) * 34;
#pragma unroll
        for (int db = 0; db < 8; db++) {
            o_[db][0] += p[db * 4]; o_[db][1] += p[db * 4 + 1];
            o_[db][2] += p[db * 4 + 2]; o_[db][3] += p[db * 4 + 3];
        }
        z0 += p[32]; z1 += p[33];
#pragma unroll
        for (int off = 1; off <= 2; off <<= 1) {
            z0 += __shfl_xor_sync(FULLMASK, z0, off);
            z1 += __shfl_xor_sync(FULLMASK, z1, off);
        }
        float* P0 = g_po + ((size_t)(sp * VV + v) * NN + r0) * 64;
        float* P1 = P0 + 8 * 64;
#pragma unroll
        for (int db = 0; db < 8; db++) {
            *(float2*)&P0[db * 8 + 2 * t] = make_float2(o_[db][0], o_[db][1]);
            *(float2*)&P1[db * 8 + 2 * t] = make_float2(o_[db][2], o_[db][3]);
        }
        if (t == 0) {
            int ri = (sp * VV + v) * NN + r0;
            g_pl[ri] = z0;
            g_pl[ri + 8] = z1;
        }
    }
}

// ------------------- K2c: combine j-split partials, normalize, ELU -------------------
__global__ void __launch_bounds__(256) k2c_combine() {
    int tid = threadIdx.x, warp = tid >> 5, lane = tid & 31;
    int gw = blockIdx.x * 8 + warp;
    float n0 = 0.f, n1 = 0.f, z = 0.f;
#pragma unroll
    for (int s = 0; s < JSPLIT; s++) {
        const float* p = g_po + ((size_t)s * (VV * NN) + gw) * 64;
        n0 += p[lane];
        n1 += p[lane + 32];
        z += __ldg(&g_pl[s * (VV * NN) + gw]);
    }
    float inv = 1.f / z;
    float r0 = n0 * inv, r1 = n1 * inv;
    r0 = (r0 > 0.f) ? r0 : (__expf(r0) - 1.f);
    r1 = (r1 > 0.f) ? r1 : (__expf(r1) - 1.f);
    g_hgat[(size_t)gw * 64 + lane]      = r0;
    g_hgat[(size_t)gw * 64 + lane + 32] = r1;
}

// ------------------- K3: qkv, tensor-core, split over q/k/v, smem-staged A -------------------
#define BPAD 68
#define APAD 72
#define K3_SMEM ((64 * BPAD + 64 * APAD) * 4)

__global__ void __launch_bounds__(128) k3_qkv(const float* __restrict__ Wqkv,
                                              const float* __restrict__ bqkv) {
    extern __shared__ float sm3[];
    float* Bsm = sm3;                 // [64 n][BPAD], cols perm(k)
    float* Asm = sm3 + 64 * BPAD;     // [64 row][APAD], cols perm(k)
    int tid = threadIdx.x, warp = tid >> 5, lane = tid & 31;
    int g = lane >> 2, t = lane & 3;
    int sec = blockIdx.y;            // 0=q, 1=k, 2=v
    int row0 = blockIdx.x * 64 + warp * 16;

    // stage A tile (64 rows of g_hgat) via coalesced cp.async; permute cols at STS
    // NOTE: cp.async can't permute, so do LDG.128 + permuted STS.128: since permcol
    // maps 4-aligned groups {4c..4c+3} -> {4c..4c+3} only when... it doesn't; use
    // scalar-free trick: permcol maps pairs, so a float4 at logical cols [8m..8m+3]
    // scatters. Instead load float4 and store 4 scalars at permuted cols (conflict
    // pattern: same as k2's k1-store, acceptable in a staging loop).
    const float* Ag = g_hgat + (size_t)(blockIdx.x * 64) * 64;
    for (int i = tid; i < 1024; i += 128) {
        int r = i >> 4, c4 = (i & 15) * 4;
        float4 a4 = *(const float4*)(Ag + r * 64 + c4);
        float* dst = Asm + r * APAD;
        dst[permcol(c4)]     = __uint_as_float(f2tf(a4.x));
        dst[permcol(c4 + 1)] = __uint_as_float(f2tf(a4.y));
        dst[permcol(c4 + 2)] = __uint_as_float(f2tf(a4.z));
        dst[permcol(c4 + 3)] = __uint_as_float(f2tf(a4.w));
    }
    // stage B (coalesced LDG, permuted STS)
    for (int i = tid; i < 64 * 64; i += 128) {
        int k = i >> 6, n = i & 63;
        Bsm[n * BPAD + permcol(k)] = tfround(Wqkv[k * 192 + sec * 64 + n]);
    }
    __syncthreads();

    // A fragments from smem: one LDS.64 each (pad 72 -> conflict-free)
    uint32_t af[8][4];
    {
        int ar0 = (warp * 16 + g) * APAD;
        int ar1 = (warp * 16 + g + 8) * APAD;
#pragma unroll
        for (int kc = 0; kc < 8; kc++) {
            float2 a0 = *(const float2*)&Asm[ar0 + kc * 8 + 2 * t];
            float2 a1 = *(const float2*)&Asm[ar1 + kc * 8 + 2 * t];
            af[kc][0] = __float_as_uint(a0.x);
            af[kc][1] = __float_as_uint(a1.x);
            af[kc][2] = __float_as_uint(a0.y);
            af[kc][3] = __float_as_uint(a1.y);
        }
    }
    float s[8][4];
#pragma unroll
    for (int nb = 0; nb < 8; nb++) { s[nb][0] = s[nb][1] = s[nb][2] = s[nb][3] = 0.f; }
#pragma unroll
    for (int kc = 0; kc < 8; kc++) {
#pragma unroll
        for (int nb = 0; nb < 8; nb++) {
            float2 b = *(const float2*)&Bsm[(nb * 8 + g) * BPAD + kc * 8 + 2 * t];
            mma_tf32(s[nb], af[kc], __float_as_uint(b.x), __float_as_uint(b.y));
        }
    }
    size_t b0 = (size_t)row0 * 64;
    size_t b1 = (size_t)(row0 + 8) * 64;
#pragma unroll
    for (int nb = 0; nb < 8; nb++) {
        int cl0 = nb * 8 + 2 * t, cl1 = cl0 + 1;
        float bi0 = __ldg(bqkv + sec * 64 + cl0), bi1 = __ldg(bqkv + sec * 64 + cl1);
        float v00 = s[nb][0] + bi0, v01 = s[nb][1] + bi1;
        float v10 = s[nb][2] + bi0, v11 = s[nb][3] + bi1;
        if (sec == 0) {
            int p0 = permcol(cl0), p1 = permcol(cl1);
            g_q[b0 + g * 64 + p0] = tfround(v00 * 0.125f);
            g_q[b0 + g * 64 + p1] = tfround(v01 * 0.125f);
            g_q[b1 + g * 64 + p0] = tfround(v10 * 0.125f);
            g_q[b1 + g * 64 + p1] = tfround(v11 * 0.125f);
        } else if (sec == 1) {
            int p0 = permcol(cl0), p1 = permcol(cl1);
            g_k[b0 + g * 64 + p0] = tfround(v00);
            g_k[b0 + g * 64 + p1] = tfround(v01);
            g_k[b1 + g * 64 + p0] = tfround(v10);
            g_k[b1 + g * 64 + p1] = tfround(v11);
        } else {
            size_t tb = (size_t)(row0 >> 6) * 4096;
            int ls0 = permcol((row0 & 63) + g);
            int ls1 = permcol((row0 & 63) + g + 8);
            g_v[tb + (size_t)cl0 * 64 + ls0] = tfround(v00);
            g_v[tb + (size_t)cl1 * 64 + ls0] = tfround(v01);
            g_v[tb + (size_t)cl0 * 64 + ls1] = tfround(v10);
            g_v[tb + (size_t)cl1 * 64 + ls1] = tfround(v11);
        }
    }
}

// ------------------- K4: flash attention (R11 form: BM=64, 128 thr, 3 blk/SM) -------------------
#define KPAD 72
#define VPAD 72
#define K4_SMEM ((2 * 64 * KPAD + 2 * 64 * VPAD) * 4)

__global__ void __launch_bounds__(128, 3) k4_attn() {
    extern __shared__ float dyn[];
    float* Kbuf[2] = {dyn, dyn + 64 * KPAD};
    float* Vbuf[2] = {dyn + 2 * 64 * KPAD, dyn + 2 * 64 * KPAD + 64 * VPAD};
    int tid = threadIdx.x, lane = tid & 31, warp = tid >> 5;
    int g = lane >> 2, t = lane & 3;
    int view = blockIdx.y;
    int row0 = blockIdx.x * 64;
    int sp = blockIdx.z;
    const int NT = NN / 64 / SPLITS;   // 12
    int kt0 = sp * NT;
    size_t vbase = (size_t)view * NN * 64;

    uint32_t qf[8][4];
    {
        const float* Q = g_q + vbase + (size_t)(row0 + warp * 16) * 64;
        const float2* Qa = (const float2*)(Q + g * 64);
        const float2* Qb = (const float2*)(Q + (g + 8) * 64);
#pragma unroll
        for (int kc = 0; kc < 8; kc++) {
            float2 qa = Qa[kc * 4 + t];
            float2 qb = Qb[kc * 4 + t];
            qf[kc][0] = __float_as_uint(qa.x);
            qf[kc][1] = __float_as_uint(qb.x);
            qf[kc][2] = __float_as_uint(qa.y);
            qf[kc][3] = __float_as_uint(qb.y);
        }
    }
    float m0 = NEGBIG, m1 = NEGBIG, l0 = 0.f, l1 = 0.f;
    float o[8][4];
#pragma unroll
    for (int db = 0; db < 8; db++) { o[db][0] = o[db][1] = o[db][2] = o[db][3] = 0.f; }

    auto load_tile = [&](int kt, int buf) {
        const float* Kg = g_k + vbase + (size_t)kt * 4096;
        const float* Vg = g_v + vbase + (size_t)kt * 4096;
        for (int i = tid; i < 1024; i += 128) {
            int r = i >> 4, c = (i & 15) * 4;
            cp16(&Kbuf[buf][r * KPAD + c], Kg + r * 64 + c);
            cp16(&Vbuf[buf][r * VPAD + c], Vg + r * 64 + c);
        }
        asm volatile("cp.async.commit_group;\n");
    };
    load_tile(kt0, 0);

    for (int it = 0; it < NT; it++) {
        int buf = it & 1;
        __syncthreads();
        if (it + 1 < NT) {
            load_tile(kt0 + it + 1, buf ^ 1);
            asm volatile("cp.async.wait_group 1;\n");
        } else {
            asm volatile("cp.async.wait_group 0;\n");
        }
        __syncthreads();
        float* Ksm = Kbuf[buf];
        float* Vsm = Vbuf[buf];

        float s[8][4];
#pragma unroll
        for (int nb = 0; nb < 8; nb++) { s[nb][0] = s[nb][1] = s[nb][2] = s[nb][3] = 0.f; }
#pragma unroll
        for (int kc = 0; kc < 8; kc++) {
#pragma unroll
            for (int nb = 0; nb < 8; nb++) {
                float2 kv = *(const float2*)&Ksm[(nb * 8 + g) * KPAD + kc * 8 + 2 * t];
                mma_tf32(s[nb], qf[kc], __float_as_uint(kv.x), __float_as_uint(kv.y));
            }
        }
        __syncthreads();

        float tm0 = NEGBIG, tm1 = NEGBIG;
#pragma unroll
        for (int nb = 0; nb < 8; nb++) {
            tm0 = fmaxf(tm0, fmaxf(s[nb][0], s[nb][1]));
            tm1 = fmaxf(tm1, fmaxf(s[nb][2], s[nb][3]));
        }
#pragma unroll
        for (int off = 1; off <= 2; off <<= 1) {
            tm0 = fmaxf(tm0, __shfl_xor_sync(FULLMASK, tm0, off));
            tm1 = fmaxf(tm1, __shfl_xor_sync(FULLMASK, tm1, off));
        }
        float nm0 = fmaxf(m0, tm0), nm1 = fmaxf(m1, tm1);
        float c0 = __expf(m0 - nm0), c1 = __expf(m1 - nm1);
        float r0 = 0.f, r1 = 0.f;
#pragma unroll
        for (int nb = 0; nb < 8; nb++) {
            s[nb][0] = __expf(s[nb][0] - nm0);
            s[nb][1] = __expf(s[nb][1] - nm0);
            s[nb][2] = __expf(s[nb][2] - nm1);
            s[nb][3] = __expf(s[nb][3] - nm1);
            r0 += s[nb][0] + s[nb][1];
            r1 += s[nb][2] + s[nb][3];
        }
#pragma unroll
        for (int off = 1; off <= 2; off <<= 1) {
            r0 += __shfl_xor_sync(FULLMASK, r0, off);
            r1 += __shfl_xor_sync(FULLMASK, r1, off);
        }
        l0 = l0 * c0 + r0;
        l1 = l1 * c1 + r1;
#pragma unroll
        for (int db = 0; db < 8; db++) {
            o[db][0] *= c0; o[db][1] *= c0; o[db][2] *= c1; o[db][3] *= c1;
        }
        m0 = nm0; m1 = nm1;

        float* Pw = Ksm + warp * 16 * KPAD;
        int ps0 = ((2 * t) & 3) * 2 + (t >> 1);
        int ps1 = ((2 * t + 1) & 3) * 2 + (t >> 1);
#pragma unroll
        for (int nb = 0; nb < 8; nb++) {
            Pw[g * KPAD + nb * 8 + ps0]       = tfround(s[nb][0]);
            Pw[g * KPAD + nb * 8 + ps1]       = tfround(s[nb][1]);
            Pw[(g + 8) * KPAD + nb * 8 + ps0] = tfround(s[nb][2]);
            Pw[(g + 8) * KPAD + nb * 8 + ps1] = tfround(s[nb][3]);
        }
        __syncwarp();

#pragma unroll
        for (int kc = 0; kc < 8; kc++) {
            float2 pa = *(const float2*)&Pw[g * KPAD + kc * 8 + 2 * t];
            float2 pb = *(const float2*)&Pw[(g + 8) * KPAD + kc * 8 + 2 * t];
            uint32_t af[4] = {__float_as_uint(pa.x), __float_as_uint(pb.x),
                              __float_as_uint(pa.y), __float_as_uint(pb.y)};
#pragma unroll
            for (int db = 0; db < 8; db++) {
                float2 vv = *(const float2*)&Vsm[(db * 8 + g) * VPAD + kc * 8 + 2 * t];
                mma_tf32(o[db], af, __float_as_uint(vv.x), __float_as_uint(vv.y));
            }
        }
    }
    float* P0 = g_po + ((size_t)(sp * VV + view) * NN + row0 + warp * 16) * 64;
    float* P1 = P0 + 8 * 64;
#pragma unroll
    for (int db = 0; db < 8; db++) {
        *(float2*)&P0[g * 64 + db * 8 + 2 * t] = make_float2(o[db][0], o[db][1]);
        *(float2*)&P1[g * 64 + db * 8 + 2 * t] = make_float2(o[db][2], o[db][3]);
    }
    if (t == 0) {
        int ri = (sp * VV + view) * NN + row0 + warp * 16;
        g_pm[ri + g] = m0;     g_pl[ri + g] = l0;
        g_pm[ri + g + 8] = m1; g_pl[ri + g + 8] = l1;
    }
}

// ------------------- K4c: split-K combine -------------------
__global__ void __launch_bounds__(256) k4c_combine() {
    int tid = threadIdx.x, warp = tid >> 5, lane = tid & 31;
    int gw = blockIdx.x * 8 + warp;
    float ms[SPLITS];
    float M = NEGBIG;
#pragma unroll
    for (int s = 0; s < SPLITS; s++) {
        ms[s] = __ldg(&g_pm[s * (VV * NN) + gw]);
        M = fmaxf(M, ms[s]);
    }
    float c[SPLITS];
    float den = 0.f;
#pragma unroll
    for (int s = 0; s < SPLITS; s++) {
        c[s] = __expf(ms[s] - M);
        den += __ldg(&g_pl[s * (VV * NN) + gw]) * c[s];
    }
    float inv = 1.f / den;
    float n0 = 0.f, n1 = 0.f;
#pragma unroll
    for (int s = 0; s < SPLITS; s++) {
        const float* p = g_po + ((size_t)s * (VV * NN) + gw) * 64;
        n0 += p[lane] * c[s];
        n1 += p[lane + 32] * c[s];
    }
    g_vals[(size_t)gw * 64 + lane]      = n0 * inv;
    g_vals[(size_t)gw * 64 + lane + 32] = n1 * inv;
}

// ------------------- K5: o-proj + fusion -------------------
__global__ void __launch_bounds__(256) k5_fuse(const float* __restrict__ Wo,
                                               const float* __restrict__ bo,
                                               const float* __restrict__ Wf,
                                               const float* __restrict__ bf,
                                               float* __restrict__ out) {
    __shared__ float Wos[64 * 64];
    __shared__ float Wfs[64 * 64];
    int tid = threadIdx.x;
    for (int i = tid; i < 64 * 64; i += 256) { Wos[i] = Wo[i]; Wfs[i] = Wf[i]; }
    __syncthreads();
    int node = blockIdx.x * 8 + (tid >> 5);
    int lane = tid & 31;
    float bo0 = __ldg(bo + lane), bo1 = __ldg(bo + lane + 32);
    float bf0 = __ldg(bf + lane), bf1 = __ldg(bf + lane + 32);
    float fs0 = 0.f, fs1 = 0.f;
    float* vh_out = out + 1024 * 64;
    for (int v = 0; v < VV; v++) {
        const float* vr = g_vals + ((size_t)v * NN + node) * 64;
        float x0 = vr[lane], x1 = vr[lane + 32];
        float o0 = bo0, o1 = bo1;
#pragma unroll
        for (int k = 0; k < 64; k++) {
            float xk = __shfl_sync(FULLMASK, (k < 32) ? x0 : x1, k & 31);
            o0 += xk * Wos[k * 64 + lane];
            o1 += xk * Wos[k * 64 + lane + 32];
        }
        const float* hg = g_hgat + ((size_t)v * NN + node) * 64;
        float hf0 = 0.8f * o0 + 0.2f * hg[lane];
        float hf1 = 0.8f * o1 + 0.2f * hg[lane + 32];
        float w0 = bf0, w1 = bf1;
#pragma unroll
        for (int k = 0; k < 64; k++) {
            float hk = __shfl_sync(FULLMASK, (k < 32) ? hf0 : hf1, k & 31);
            w0 += hk * Wfs[k * 64 + lane];
            w1 += hk * Wfs[k * 64 + lane + 32];
        }
        w0 = 1.f / (1.f + __expf(-w0));
        w1 = 1.f / (1.f + __expf(-w1));
        float hid0 = w0 * hf0, hid1 = w1 * hf1;
        fs0 += hid0; fs1 += hid1;
        float* vh = vh_out + ((size_t)v * NN + node) * 64;
        vh[lane]      = 0.5f * hid0 + 0.5f * hf0;
        vh[lane + 32] = 0.5f * hid1 + 0.5f * hf1;
    }
    if (node >= 2048) {
        float* fo = out + (size_t)(node - 2048) * 64;
        fo[lane] = fs0;
        fo[lane + 32] = fs1;
    }
}

// ------------------- launch -------------------
extern "C" void kernel_launch(void* const* d_in, const int* in_sizes, int n_in,
                              void* d_out, int out_size) {
    const float* adj  = (const float*)d_in[0];
    const float* nf   = (const float*)d_in[1];
    const float* W    = (const float*)d_in[2];
    const float* a    = (const float*)d_in[3];
    const float* Wqkv = (const float*)d_in[4];
    const float* bqkv = (const float*)d_in[5];
    const float* Wo   = (const float*)d_in[6];
    const float* bo   = (const float*)d_in[7];
    const float* Wf   = (const float*)d_in[8];
    const float* bf   = (const float*)d_in[9];
    float* out = (float*)d_out;

    cudaFuncSetAttribute(k2_gat, cudaFuncAttributeMaxDynamicSharedMemorySize, K2_SMEM);
    cudaFuncSetAttribute(k3_qkv, cudaFuncAttributeMaxDynamicSharedMemorySize, K3_SMEM);
    cudaFuncSetAttribute(k4_attn, cudaFuncAttributeMaxDynamicSharedMemorySize, K4_SMEM);

    k1_wh<<<NN / 8, 256>>>(nf, W, a);
    k2_gat<<<dim3(NN / 64, VV, JSPLIT), 256, K2_SMEM>>>(adj);
    k2c_combine<<<VV * NN / 8, 256>>>();
    k3_qkv<<<dim3(VV * NN / 64, 3), 128, K3_SMEM>>>(Wqkv, bqkv);
    k4_attn<<<dim3(NN / 64, VV, SPLITS), 128, K4_SMEM>>>();
    k4c_combine<<<VV * NN / 8, 256>>>();
    k5_fuse<<<NN / 8, 256>>>(Wo, bo, Wf, bf, out);
}

// round 17
// speedup vs baseline: 1.0148x; 1.0148x over previous
#include <cuda_runtime.h>
#include <cstdint>

#define NN 3072
#define HH 64
#define VV 4
#define SPLITS 4
#define JSPLIT 4
#define JLOC (NN / JSPLIT)
#define FULLMASK 0xFFFFFFFFu
#define NEGBIG (-1e30f)

// ------------------- scratch (device globals; no allocations) -------------------
__device__ float g_Wh[NN * HH];       // [tile][h=64][perm(j)=64], tf32-rounded
__device__ float g_el[NN];
__device__ float g_er[NN];
__device__ float g_ermp[NN / 8];      // per-k1-block max of er (384 entries)
__device__ float g_hgat[VV * NN * HH];
__device__ float g_q[VV * NN * HH];   // tf32-rounded, cols pair-permuted
__device__ float g_k[VV * NN * HH];   // tf32-rounded, cols pair-permuted
__device__ float g_v[VV * NN * HH];   // [tile][d=64][perm(seq)=64], tf32-rounded
__device__ float g_vals[VV * NN * HH];
__device__ float g_po[8 * VV * NN * HH];
__device__ float g_pm[8 * VV * NN];
__device__ float g_pl[8 * VV * NN];

__device__ __forceinline__ uint32_t f2tf(float f) {
    uint32_t u;
    asm("cvt.rna.tf32.f32 %0, %1;" : "=r"(u) : "f"(f));
    return u;
}
__device__ __forceinline__ float tfround(float f) { return __uint_as_float(f2tf(f)); }

__device__ __forceinline__ int permcol(int c) {
    return (c & ~7) | (((c & 3) << 1) | ((c >> 2) & 1));
}

__device__ __forceinline__ void mma_tf32(float* d, const uint32_t* a, uint32_t b0, uint32_t b1) {
    asm volatile(
        "mma.sync.aligned.m16n8k8.row.col.f32.tf32.tf32.f32 "
        "{%0,%1,%2,%3}, {%4,%5,%6,%7}, {%8,%9}, {%0,%1,%2,%3};"
        : "+f"(d[0]), "+f"(d[1]), "+f"(d[2]), "+f"(d[3])
        : "r"(a[0]), "r"(a[1]), "r"(a[2]), "r"(a[3]), "r"(b0), "r"(b1));
}

__device__ __forceinline__ void cp16(float* dst, const float* src) {
    uint32_t d = (uint32_t)__cvta_generic_to_shared(dst);
    asm volatile("cp.async.ca.shared.global [%0], [%1], 16;\n" :: "r"(d), "l"(src));
}
__device__ __forceinline__ void cp16cg(float* dst, const float* src) {
    uint32_t d = (uint32_t)__cvta_generic_to_shared(dst);
    asm volatile("cp.async.cg.shared.global [%0], [%1], 16;\n" :: "r"(d), "l"(src));
}

// ------------------- K1: Wh = X @ W ; el ; er ; per-block er max -------------------
__global__ void k1_wh(const float* __restrict__ x, const float* __restrict__ W,
                      const float* __restrict__ a) {
    __shared__ float Wsm[64 * 64];
    __shared__ float a_sm[128];
    __shared__ float wmax[8];
    int tid = threadIdx.x;
    for (int i = tid; i < 64 * 64; i += 256) Wsm[i] = W[i];
    if (tid < 128) a_sm[tid] = a[tid];
    __syncthreads();
    int warp = tid >> 5, lane = tid & 31;
    int row = blockIdx.x * 8 + warp;
    const float* xr = x + row * 64;
    float x0 = xr[lane], x1 = xr[lane + 32];
    float wh0 = 0.f, wh1 = 0.f;
#pragma unroll
    for (int k = 0; k < 64; k++) {
        float xk = __shfl_sync(FULLMASK, (k < 32) ? x0 : x1, k & 31);
        wh0 += xk * Wsm[k * 64 + lane];
        wh1 += xk * Wsm[k * 64 + lane + 32];
    }
    size_t tb = (size_t)(row >> 6) * 4096;
    int pj = permcol(row & 63);
    g_Wh[tb + (size_t)lane * 64 + pj]        = tfround(wh0);
    g_Wh[tb + (size_t)(lane + 32) * 64 + pj] = tfround(wh1);
    float pl = wh0 * a_sm[lane] + wh1 * a_sm[lane + 32];
    float pr = wh0 * a_sm[64 + lane] + wh1 * a_sm[96 + lane];
#pragma unroll
    for (int o = 16; o; o >>= 1) {
        pl += __shfl_xor_sync(FULLMASK, pl, o);
        pr += __shfl_xor_sync(FULLMASK, pr, o);
    }
    if (lane == 0) { g_el[row] = pl; g_er[row] = pr; wmax[warp] = pr; }
    __syncthreads();
    if (tid == 0) {
        float m = wmax[0];
#pragma unroll
        for (int i = 1; i < 8; i++) m = fmaxf(m, wmax[i]);
        g_ermp[blockIdx.x] = m;
    }
}

// ------------------- K2: tensor-core GAT, cp.async-staged, float2 B-frags -------------------
#define WHPAD 72
#define ADJPAD 132
#define K2_SMEM ((2 * 64 * WHPAD + 2 * 64 * ADJPAD + JLOC) * 4)

__global__ void __launch_bounds__(256) k2_gat(const float* __restrict__ adj) {
    extern __shared__ float sm2[];
    float* whs0  = sm2;                          // [2 tile][64 h][WHPAD] (perm j cols)
    float* adjs0 = sm2 + 2 * 64 * WHPAD;         // [2 buf][64 row][ADJPAD]
    float* ers   = adjs0 + 2 * 64 * ADJPAD;      // [JLOC]
    __shared__ float wred[8];
    int tid = threadIdx.x, warp = tid >> 5, lane = tid & 31;
    int g = lane >> 2, t = lane & 3;
    int grp = warp >> 2, rw = warp & 3;
    int v = blockIdx.y, row0 = blockIdx.x * 64, sp = blockIdx.z;
    const int JT_PER = NN / 128 / JSPLIT;   // 6
    int jt0 = sp * JT_PER;

    {
        const float* Asrc = adj + ((size_t)v * NN + row0) * NN + (size_t)jt0 * 128;
        for (int i = tid; i < 2048; i += 256) {
            int r = i >> 5, c4 = i & 31;
            cp16cg(&adjs0[r * ADJPAD + c4 * 4], Asrc + (size_t)r * NN + c4 * 4);
        }
        asm volatile("cp.async.commit_group;\n");
    }

    // er_max from k1's per-block partials (384 values, exact same max)
    float mx = NEGBIG;
    for (int i = tid; i < NN / 8; i += 256) mx = fmaxf(mx, __ldg(&g_ermp[i]));
#pragma unroll
    for (int o = 16; o; o >>= 1) mx = fmaxf(mx, __shfl_xor_sync(FULLMASK, mx, o));
    if (lane == 0) wred[warp] = mx;
    __syncthreads();
    float ermax = wred[0];
#pragma unroll
    for (int i = 1; i < 8; i++) ermax = fmaxf(ermax, wred[i]);

    for (int i = tid; i < JLOC; i += 256) ers[i] = __ldg(&g_er[sp * JLOC + i]);

    int r0 = row0 + rw * 16 + g;
    float el0 = __ldg(&g_el[r0]), el1 = __ldg(&g_el[r0 + 8]);
    float m0 = el0 + ermax; m0 = (m0 > 0.f) ? m0 : 0.2f * m0;
    float m1 = el1 + ermax; m1 = (m1 > 0.f) ? m1 : 0.2f * m1;

    float o_[8][4];
#pragma unroll
    for (int db = 0; db < 8; db++) { o_[db][0] = o_[db][1] = o_[db][2] = o_[db][3] = 0.f; }
    float z0 = 0.f, z1 = 0.f;
    int lr0 = rw * 16 + g, lr1 = lr0 + 8;

    for (int jj = 0; jj < JT_PER; jj++) {
        int jt2 = jt0 + jj;
        __syncthreads();
        const float* Wsrc = g_Wh + (size_t)jt2 * 2 * 4096;
        for (int i = tid; i < 2048; i += 256) {
            int b = i >> 10, ii = i & 1023;
            int h = ii >> 4, c4 = ii & 15;
            cp16(&whs0[b * 64 * WHPAD + h * WHPAD + c4 * 4], Wsrc + b * 4096 + h * 64 + c4 * 4);
        }
        asm volatile("cp.async.commit_group;\n");
        if (jj + 1 < JT_PER) {
            const float* Asrc = adj + ((size_t)v * NN + row0) * NN + (size_t)(jt2 + 1) * 128;
            float* ad = adjs0 + ((jj + 1) & 1) * 64 * ADJPAD;
            for (int i = tid; i < 2048; i += 256) {
                int r = i >> 5, c4 = i & 31;
                cp16cg(&ad[r * ADJPAD + c4 * 4], Asrc + (size_t)r * NN + c4 * 4);
            }
            asm volatile("cp.async.commit_group;\n");
            asm volatile("cp.async.wait_group 1;\n");
        } else {
            asm volatile("cp.async.wait_group 0;\n");
        }
        __syncthreads();
        const float* wh = whs0 + grp * 64 * WHPAD;
        const float* ad = adjs0 + (jj & 1) * 64 * ADJPAD;
        int lj0 = jj * 128 + grp * 64;
        int ljc0 = grp * 64;
#pragma unroll
        for (int kc = 0; kc < 8; kc++) {
            int ljc = ljc0 + kc * 8;
            float a00 = ad[lr0 * ADJPAD + ljc + t];
            float a10 = ad[lr1 * ADJPAD + ljc + t];
            float a01 = ad[lr0 * ADJPAD + ljc + t + 4];
            float a11 = ad[lr1 * ADJPAD + ljc + t + 4];
            int lj = lj0 + kc * 8;
            float erA = ers[lj + t], erB = ers[lj + t + 4];
            float eA0 = el0 + erA; eA0 = (eA0 > 0.f) ? eA0 : 0.2f * eA0;
            float eA1 = el1 + erA; eA1 = (eA1 > 0.f) ? eA1 : 0.2f * eA1;
            float eB0 = el0 + erB; eB0 = (eB0 > 0.f) ? eB0 : 0.2f * eB0;
            float eB1 = el1 + erB; eB1 = (eB1 > 0.f) ? eB1 : 0.2f * eB1;
            float p00 = (a00 > 0.f) ? tfround(__expf(eA0 - m0)) : 0.f;
            float p10 = (a10 > 0.f) ? tfround(__expf(eA1 - m1)) : 0.f;
            float p01 = (a01 > 0.f) ? tfround(__expf(eB0 - m0)) : 0.f;
            float p11 = (a11 > 0.f) ? tfround(__expf(eB1 - m1)) : 0.f;
            z0 += p00 + p01;
            z1 += p10 + p11;
            uint32_t af[4] = {__float_as_uint(p00), __float_as_uint(p10),
                              __float_as_uint(p01), __float_as_uint(p11)};
#pragma unroll
            for (int db = 0; db < 8; db++) {
                float2 kv = *(const float2*)&wh[(db * 8 + g) * WHPAD + kc * 8 + 2 * t];
                mma_tf32(o_[db], af, __float_as_uint(kv.x), __float_as_uint(kv.y));
            }
        }
    }
    __syncthreads();
    float* scr = whs0;
    if (grp == 1) {
        float* p = scr + (rw * 32 + lane) * 34;
#pragma unroll
        for (int db = 0; db < 8; db++) {
            p[db * 4] = o_[db][0]; p[db * 4 + 1] = o_[db][1];
            p[db * 4 + 2] = o_[db][2]; p[db * 4 + 3] = o_[db][3];
        }
        p[32] = z0; p[33] = z1;
    }
    __syncthreads();
    if (grp == 0) {
        const float* p = scr + (rw * 32 + lane) * 34;
#pragma unroll
        for (int db = 0; db < 8; db++) {
            o_[db][0] += p[db * 4]; o_[db][1] += p[db * 4 + 1];
            o_[db][2] += p[db * 4 + 2]; o_[db][3] += p[db * 4 + 3];
        }
        z0 += p[32]; z1 += p[33];
#pragma unroll
        for (int off = 1; off <= 2; off <<= 1) {
            z0 += __shfl_xor_sync(FULLMASK, z0, off);
            z1 += __shfl_xor_sync(FULLMASK, z1, off);
        }
        float* P0 = g_po + ((size_t)(sp * VV + v) * NN + r0) * 64;
        float* P1 = P0 + 8 * 64;
#pragma unroll
        for (int db = 0; db < 8; db++) {
            *(float2*)&P0[db * 8 + 2 * t] = make_float2(o_[db][0], o_[db][1]);
            *(float2*)&P1[db * 8 + 2 * t] = make_float2(o_[db][2], o_[db][3]);
        }
        if (t == 0) {
            int ri = (sp * VV + v) * NN + r0;
            g_pl[ri] = z0;
            g_pl[ri + 8] = z1;
        }
    }
}

// ------------------- K2c: combine j-split partials, normalize, ELU -------------------
__global__ void __launch_bounds__(256) k2c_combine() {
    int tid = threadIdx.x, warp = tid >> 5, lane = tid & 31;
    int gw = blockIdx.x * 8 + warp;
    float n0 = 0.f, n1 = 0.f, z = 0.f;
#pragma unroll
    for (int s = 0; s < JSPLIT; s++) {
        const float* p = g_po + ((size_t)s * (VV * NN) + gw) * 64;
        n0 += p[lane];
        n1 += p[lane + 32];
        z += __ldg(&g_pl[s * (VV * NN) + gw]);
    }
    float inv = 1.f / z;
    float r0 = n0 * inv, r1 = n1 * inv;
    r0 = (r0 > 0.f) ? r0 : (__expf(r0) - 1.f);
    r1 = (r1 > 0.f) ? r1 : (__expf(r1) - 1.f);
    g_hgat[(size_t)gw * 64 + lane]      = r0;
    g_hgat[(size_t)gw * 64 + lane + 32] = r1;
}

// ------------------- K3: qkv, tensor-core, split over q/k/v (R15 form) -------------------
#define BPAD 68
#define K3_SMEM (64 * BPAD * 4)

__global__ void __launch_bounds__(128) k3_qkv(const float* __restrict__ Wqkv,
                                              const float* __restrict__ bqkv) {
    extern __shared__ float Bsm[];
    int tid = threadIdx.x, warp = tid >> 5, lane = tid & 31;
    int g = lane >> 2, t = lane & 3;
    int sec = blockIdx.y;            // 0=q, 1=k, 2=v
    for (int i = tid; i < 64 * 64; i += 128) {
        int k = i >> 6, n = i & 63;
        Bsm[n * BPAD + permcol(k)] = tfround(Wqkv[k * 192 + sec * 64 + n]);
    }
    int row0 = blockIdx.x * 64 + warp * 16;
    uint32_t af[8][4];
    {
        const float* A = g_hgat + (size_t)row0 * 64;
#pragma unroll
        for (int kc = 0; kc < 8; kc++) {
            af[kc][0] = f2tf(A[g * 64 + kc * 8 + t]);
            af[kc][1] = f2tf(A[(g + 8) * 64 + kc * 8 + t]);
            af[kc][2] = f2tf(A[g * 64 + kc * 8 + t + 4]);
            af[kc][3] = f2tf(A[(g + 8) * 64 + kc * 8 + t + 4]);
        }
    }
    float s[8][4];
#pragma unroll
    for (int nb = 0; nb < 8; nb++) { s[nb][0] = s[nb][1] = s[nb][2] = s[nb][3] = 0.f; }
    __syncthreads();
#pragma unroll
    for (int kc = 0; kc < 8; kc++) {
#pragma unroll
        for (int nb = 0; nb < 8; nb++) {
            float2 b = *(const float2*)&Bsm[(nb * 8 + g) * BPAD + kc * 8 + 2 * t];
            mma_tf32(s[nb], af[kc], __float_as_uint(b.x), __float_as_uint(b.y));
        }
    }
    size_t b0 = (size_t)row0 * 64;
    size_t b1 = (size_t)(row0 + 8) * 64;
#pragma unroll
    for (int nb = 0; nb < 8; nb++) {
        int cl0 = nb * 8 + 2 * t, cl1 = cl0 + 1;
        float bi0 = __ldg(bqkv + sec * 64 + cl0), bi1 = __ldg(bqkv + sec * 64 + cl1);
        float v00 = s[nb][0] + bi0, v01 = s[nb][1] + bi1;
        float v10 = s[nb][2] + bi0, v11 = s[nb][3] + bi1;
        if (sec == 0) {
            int p0 = permcol(cl0), p1 = permcol(cl1);
            g_q[b0 + g * 64 + p0] = tfround(v00 * 0.125f);
            g_q[b0 + g * 64 + p1] = tfround(v01 * 0.125f);
            g_q[b1 + g * 64 + p0] = tfround(v10 * 0.125f);
            g_q[b1 + g * 64 + p1] = tfround(v11 * 0.125f);
        } else if (sec == 1) {
            int p0 = permcol(cl0), p1 = permcol(cl1);
            g_k[b0 + g * 64 + p0] = tfround(v00);
            g_k[b0 + g * 64 + p1] = tfround(v01);
            g_k[b1 + g * 64 + p0] = tfround(v10);
            g_k[b1 + g * 64 + p1] = tfround(v11);
        } else {
            size_t tb = (size_t)(row0 >> 6) * 4096;
            int ls0 = permcol((row0 & 63) + g);
            int ls1 = permcol((row0 & 63) + g + 8);
            g_v[tb + (size_t)cl0 * 64 + ls0] = tfround(v00);
            g_v[tb + (size_t)cl1 * 64 + ls0] = tfround(v01);
            g_v[tb + (size_t)cl0 * 64 + ls1] = tfround(v10);
            g_v[tb + (size_t)cl1 * 64 + ls1] = tfround(v11);
        }
    }
}

// ------------------- K4: flash attention (BM=64, 128 thr, 3 blk/SM) -------------------
#define KPAD 72
#define VPAD 72
#define K4_SMEM ((2 * 64 * KPAD + 2 * 64 * VPAD) * 4)

__global__ void __launch_bounds__(128, 3) k4_attn() {
    extern __shared__ float dyn[];
    float* Kbuf[2] = {dyn, dyn + 64 * KPAD};
    float* Vbuf[2] = {dyn + 2 * 64 * KPAD, dyn + 2 * 64 * KPAD + 64 * VPAD};
    int tid = threadIdx.x, lane = tid & 31, warp = tid >> 5;
    int g = lane >> 2, t = lane & 3;
    int view = blockIdx.y;
    int row0 = blockIdx.x * 64;
    int sp = blockIdx.z;
    const int NT = NN / 64 / SPLITS;   // 12
    int kt0 = sp * NT;
    size_t vbase = (size_t)view * NN * 64;

    uint32_t qf[8][4];
    {
        const float* Q = g_q + vbase + (size_t)(row0 + warp * 16) * 64;
        const float2* Qa = (const float2*)(Q + g * 64);
        const float2* Qb = (const float2*)(Q + (g + 8) * 64);
#pragma unroll
        for (int kc = 0; kc < 8; kc++) {
            float2 qa = Qa[kc * 4 + t];
            float2 qb = Qb[kc * 4 + t];
            qf[kc][0] = __float_as_uint(qa.x);
            qf[kc][1] = __float_as_uint(qb.x);
            qf[kc][2] = __float_as_uint(qa.y);
            qf[kc][3] = __float_as_uint(qb.y);
        }
    }
    float m0 = NEGBIG, m1 = NEGBIG, l0 = 0.f, l1 = 0.f;
    float o[8][4];
#pragma unroll
    for (int db = 0; db < 8; db++) { o[db][0] = o[db][1] = o[db][2] = o[db][3] = 0.f; }

    auto load_tile = [&](int kt, int buf) {
        const float* Kg = g_k + vbase + (size_t)kt * 4096;
        const float* Vg = g_v + vbase + (size_t)kt * 4096;
        for (int i = tid; i < 1024; i += 128) {
            int r = i >> 4, c = (i & 15) * 4;
            cp16(&Kbuf[buf][r * KPAD + c], Kg + r * 64 + c);
            cp16(&Vbuf[buf][r * VPAD + c], Vg + r * 64 + c);
        }
        asm volatile("cp.async.commit_group;\n");
    };
    load_tile(kt0, 0);

    for (int it = 0; it < NT; it++) {
        int buf = it & 1;
        __syncthreads();
        if (it + 1 < NT) {
            load_tile(kt0 + it + 1, buf ^ 1);
            asm volatile("cp.async.wait_group 1;\n");
        } else {
            asm volatile("cp.async.wait_group 0;\n");
        }
        __syncthreads();
        float* Ksm = Kbuf[buf];
        float* Vsm = Vbuf[buf];

        float s[8][4];
#pragma unroll
        for (int nb = 0; nb < 8; nb++) { s[nb][0] = s[nb][1] = s[nb][2] = s[nb][3] = 0.f; }
#pragma unroll
        for (int kc = 0; kc < 8; kc++) {
#pragma unroll
            for (int nb = 0; nb < 8; nb++) {
                float2 kv = *(const float2*)&Ksm[(nb * 8 + g) * KPAD + kc * 8 + 2 * t];
                mma_tf32(s[nb], qf[kc], __float_as_uint(kv.x), __float_as_uint(kv.y));
            }
        }
        __syncthreads();

        float tm0 = NEGBIG, tm1 = NEGBIG;
#pragma unroll
        for (int nb = 0; nb < 8; nb++) {
            tm0 = fmaxf(tm0, fmaxf(s[nb][0], s[nb][1]));
            tm1 = fmaxf(tm1, fmaxf(s[nb][2], s[nb][3]));
        }
#pragma unroll
        for (int off = 1; off <= 2; off <<= 1) {
            tm0 = fmaxf(tm0, __shfl_xor_sync(FULLMASK, tm0, off));
            tm1 = fmaxf(tm1, __shfl_xor_sync(FULLMASK, tm1, off));
        }
        float nm0 = fmaxf(m0, tm0), nm1 = fmaxf(m1, tm1);
        float c0 = __expf(m0 - nm0), c1 = __expf(m1 - nm1);
        float r0 = 0.f, r1 = 0.f;
#pragma unroll
        for (int nb = 0; nb < 8; nb++) {
            s[nb][0] = __expf(s[nb][0] - nm0);
            s[nb][1] = __expf(s[nb][1] - nm0);
            s[nb][2] = __expf(s[nb][2] - nm1);
            s[nb][3] = __expf(s[nb][3] - nm1);
            r0 += s[nb][0] + s[nb][1];
            r1 += s[nb][2] + s[nb][3];
        }
#pragma unroll
        for (int off = 1; off <= 2; off <<= 1) {
            r0 += __shfl_xor_sync(FULLMASK, r0, off);
            r1 += __shfl_xor_sync(FULLMASK, r1, off);
        }
        l0 = l0 * c0 + r0;
        l1 = l1 * c1 + r1;
#pragma unroll
        for (int db = 0; db < 8; db++) {
            o[db][0] *= c0; o[db][1] *= c0; o[db][2] *= c1; o[db][3] *= c1;
        }
        m0 = nm0; m1 = nm1;

        float* Pw = Ksm + warp * 16 * KPAD;
        int ps0 = ((2 * t) & 3) * 2 + (t >> 1);
        int ps1 = ((2 * t + 1) & 3) * 2 + (t >> 1);
#pragma unroll
        for (int nb = 0; nb < 8; nb++) {
            Pw[g * KPAD + nb * 8 + ps0]       = tfround(s[nb][0]);
            Pw[g * KPAD + nb * 8 + ps1]       = tfround(s[nb][1]);
            Pw[(g + 8) * KPAD + nb * 8 + ps0] = tfround(s[nb][2]);
            Pw[(g + 8) * KPAD + nb * 8 + ps1] = tfround(s[nb][3]);
        }
        __syncwarp();

#pragma unroll
        for (int kc = 0; kc < 8; kc++) {
            float2 pa = *(const float2*)&Pw[g * KPAD + kc * 8 + 2 * t];
            float2 pb = *(const float2*)&Pw[(g + 8) * KPAD + kc * 8 + 2 * t];
            uint32_t af[4] = {__float_as_uint(pa.x), __float_as_uint(pb.x),
                              __float_as_uint(pa.y), __float_as_uint(pb.y)};
#pragma unroll
            for (int db = 0; db < 8; db++) {
                float2 vv = *(const float2*)&Vsm[(db * 8 + g) * VPAD + kc * 8 + 2 * t];
                mma_tf32(o[db], af, __float_as_uint(vv.x), __float_as_uint(vv.y));
            }
        }
    }
    float* P0 = g_po + ((size_t)(sp * VV + view) * NN + row0 + warp * 16) * 64;
    float* P1 = P0 + 8 * 64;
#pragma unroll
    for (int db = 0; db < 8; db++) {
        *(float2*)&P0[g * 64 + db * 8 + 2 * t] = make_float2(o[db][0], o[db][1]);
        *(float2*)&P1[g * 64 + db * 8 + 2 * t] = make_float2(o[db][2], o[db][3]);
    }
    if (t == 0) {
        int ri = (sp * VV + view) * NN + row0 + warp * 16;
        g_pm[ri + g] = m0;     g_pl[ri + g] = l0;
        g_pm[ri + g + 8] = m1; g_pl[ri + g + 8] = l1;
    }
}

// ------------------- K4c: split-K combine -------------------
__global__ void __launch_bounds__(256) k4c_combine() {
    int tid = threadIdx.x, warp = tid >> 5, lane = tid & 31;
    int gw = blockIdx.x * 8 + warp;
    float ms[SPLITS];
    float M = NEGBIG;
#pragma unroll
    for (int s = 0; s < SPLITS; s++) {
        ms[s] = __ldg(&g_pm[s * (VV * NN) + gw]);
        M = fmaxf(M, ms[s]);
    }
    float c[SPLITS];
    float den = 0.f;
#pragma unroll
    for (int s = 0; s < SPLITS; s++) {
        c[s] = __expf(ms[s] - M);
        den += __ldg(&g_pl[s * (VV * NN) + gw]) * c[s];
    }
    float inv = 1.f / den;
    float n0 = 0.f, n1 = 0.f;
#pragma unroll
    for (int s = 0; s < SPLITS; s++) {
        const float* p = g_po + ((size_t)s * (VV * NN) + gw) * 64;
        n0 += p[lane] * c[s];
        n1 += p[lane + 32] * c[s];
    }
    g_vals[(size_t)gw * 64 + lane]      = n0 * inv;
    g_vals[(size_t)gw * 64 + lane + 32] = n1 * inv;
}

// ------------------- K5: o-proj + fusion -------------------
__global__ void __launch_bounds__(256) k5_fuse(const float* __restrict__ Wo,
                                               const float* __restrict__ bo,
                                               const float* __restrict__ Wf,
                                               const float* __restrict__ bf,
                                               float* __restrict__ out) {
    __shared__ float Wos[64 * 64];
    __shared__ float Wfs[64 * 64];
    int tid = threadIdx.x;
    for (int i = tid; i < 64 * 64; i += 256) { Wos[i] = Wo[i]; Wfs[i] = Wf[i]; }
    __syncthreads();
    int node = blockIdx.x * 8 + (tid >> 5);
    int lane = tid & 31;
    float bo0 = __ldg(bo + lane), bo1 = __ldg(bo + lane + 32);
    float bf0 = __ldg(bf + lane), bf1 = __ldg(bf + lane + 32);
    float fs0 = 0.f, fs1 = 0.f;
    float* vh_out = out + 1024 * 64;
    for (int v = 0; v < VV; v++) {
        const float* vr = g_vals + ((size_t)v * NN + node) * 64;
        float x0 = vr[lane], x1 = vr[lane + 32];
        float o0 = bo0, o1 = bo1;
#pragma unroll
        for (int k = 0; k < 64; k++) {
            float xk = __shfl_sync(FULLMASK, (k < 32) ? x0 : x1, k & 31);
            o0 += xk * Wos[k * 64 + lane];
            o1 += xk * Wos[k * 64 + lane + 32];
        }
        const float* hg = g_hgat + ((size_t)v * NN + node) * 64;
        float hf0 = 0.8f * o0 + 0.2f * hg[lane];
        float hf1 = 0.8f * o1 + 0.2f * hg[lane + 32];
        float w0 = bf0, w1 = bf1;
#pragma unroll
        for (int k = 0; k < 64; k++) {
            float hk = __shfl_sync(FULLMASK, (k < 32) ? hf0 : hf1, k & 31);
            w0 += hk * Wfs[k * 64 + lane];
            w1 += hk * Wfs[k * 64 + lane + 32];
        }
        w0 = 1.f / (1.f + __expf(-w0));
        w1 = 1.f / (1.f + __expf(-w1));
        float hid0 = w0 * hf0, hid1 = w1 * hf1;
        fs0 += hid0; fs1 += hid1;
        float* vh = vh_out + ((size_t)v * NN + node) * 64;
        vh[lane]      = 0.5f * hid0 + 0.5f * hf0;
        vh[lane + 32] = 0.5f * hid1 + 0.5f * hf1;
    }
    if (node >= 2048) {
        float* fo = out + (size_t)(node - 2048) * 64;
        fo[lane] = fs0;
        fo[lane + 32] = fs1;
    }
}

// ------------------- launch -------------------
extern "C" void kernel_launch(void* const* d_in, const int* in_sizes, int n_in,
                              void* d_out, int out_size) {
    const float* adj  = (const float*)d_in[0];
    const float* nf   = (const float*)d_in[1];
    const float* W    = (const float*)d_in[2];
    const float* a    = (const float*)d_in[3];
    const float* Wqkv = (const float*)d_in[4];
    const float* bqkv = (const float*)d_in[5];
    const float* Wo   = (const float*)d_in[6];
    const float* bo   = (const float*)d_in[7];
    const float* Wf   = (const float*)d_in[8];
    const float* bf   = (const float*)d_in[9];
    float* out = (float*)d_out;

    cudaFuncSetAttribute(k2_gat, cudaFuncAttributeMaxDynamicSharedMemorySize, K2_SMEM);
    cudaFuncSetAttribute(k3_qkv, cudaFuncAttributeMaxDynamicSharedMemorySize, K3_SMEM);
    cudaFuncSetAttribute(k4_attn, cudaFuncAttributeMaxDynamicSharedMemorySize, K4_SMEM);

    k1_wh<<<NN / 8, 256>>>(nf, W, a);
    k2_gat<<<dim3(NN / 64, VV, JSPLIT), 256, K2_SMEM>>>(adj);
    k2c_combine<<<VV * NN / 8, 256>>>();
    k3_qkv<<<dim3(VV * NN / 64, 3), 128, K3_SMEM>>>(Wqkv, bqkv);
    k4_attn<<<dim3(NN / 64, VV, SPLITS), 128, K4_SMEM>>>();
    k4c_combine<<<VV * NN / 8, 256>>>();
    k5_fuse<<<NN / 8, 256>>>(Wo, bo, Wf, bf, out);
}